// round 16
// baseline (speedup 1.0000x reference)
#include <cuda_runtime.h>
#include <cuda_bf16.h>
#include <math.h>
#include <stdint.h>

// ---------------------------------------------------------------------------
// PowerIterationConv: sigma via Gram iteration in the DFT domain, grams on
// tensor cores via mma.sync m16n8k16 bf16 (fp32 accum).
//
//   Gr = R·R^T + I·I^T,  Gi = R·I^T − I·R^T  (G Hermitian every stage ->
//   6-of-9 64x64 tiles + conjugate mirror writes).  bf16 2-way split
//   (hi+lo), 3 MMAs per real product (lo·lo dropped).
//
// R16: R15's warp-fused Gr+Gi inner loop, + cp.async double-buffered chunk
// pipeline (KCH=32, two 40KB buffers) so the global->smem copy overlaps MMA.
// ---------------------------------------------------------------------------

#define CDIM 192
#define MAT (CDIM*CDIM)
#define NW 145
#define NTOT2 289.0
#define SC2 48.0
#define NTILE 6
#define NPART (NTILE*NW)        // 870
#define F0BLK 256

#define KCH 32                  // k-chunk (6 chunks cover K=192)
#define SROW 40                 // padded bf16 row stride (20 words: all-bank)
#define PL (64*SROW)            // plane elems (2560)
#define BUFE (8*PL)             // elems per buffer (8 planes)
#define SMEM_DYN (2*BUFE*2)     // 81920 bytes (2 buffers)

typedef unsigned int uint32;

// bf16 hi/lo planes, double-buffered across stages. plane: 0=Rh 1=Rl 2=Ih 3=Il
__device__ ushort g_pl[2][4][NW*MAT];
__device__ double g_f0sq;
__device__ double g_f0part[F0BLK];
__device__ double g_part[3][NPART];
__device__ double g_inv_sigma;
__device__ float2 g_phase[NW*9];

__device__ __forceinline__ uint32 smem_u32(const void* p) {
    uint32 a;
    asm("{ .reg .u64 t; cvta.to.shared.u64 t, %1; cvt.u32.u64 %0, t; }"
        : "=r"(a) : "l"(p));
    return a;
}
__device__ __forceinline__ void mma16816(float* d, const uint32* a,
                                         uint32 b0, uint32 b1) {
    asm volatile(
        "mma.sync.aligned.m16n8k16.row.col.f32.bf16.bf16.f32 "
        "{%0,%1,%2,%3}, {%4,%5,%6,%7}, {%8,%9}, {%0,%1,%2,%3};"
        : "+f"(d[0]), "+f"(d[1]), "+f"(d[2]), "+f"(d[3])
        : "r"(a[0]), "r"(a[1]), "r"(a[2]), "r"(a[3]), "r"(b0), "r"(b1));
}
__device__ __forceinline__ void split1(float v, ushort& h, ushort& l) {
    __nv_bfloat16 hb = __float2bfloat16(v);
    __nv_bfloat16 lb = __float2bfloat16(v - __bfloat162float(hb));
    h = __bfloat16_as_ushort(hb);
    l = __bfloat16_as_ushort(lb);
}
#define CP_ASYNC16(dst, src) \
    asm volatile("cp.async.cg.shared.global [%0], [%1], 16;" \
                 :: "r"(dst), "l"(src) : "memory")
#define CP_COMMIT() asm volatile("cp.async.commit_group;" ::: "memory")
#define CP_WAIT1()  asm volatile("cp.async.wait_group 1;" ::: "memory")
#define CP_WAIT0()  asm volatile("cp.async.wait_group 0;" ::: "memory")

// ---- ||K0||_F^2 partials ---------------------------------------------------
__global__ void k_f0a(const float* __restrict__ K0, int n) {
    __shared__ double sred[256];
    int per = (n + F0BLK - 1) / F0BLK;
    int base = blockIdx.x * per;
    int end = min(base + per, n);
    double s = 0.0;
    for (int i = base + threadIdx.x; i < end; i += 256) {
        float v = K0[i];
        s += (double)v * (double)v;
    }
    sred[threadIdx.x] = s;
    __syncthreads();
    for (int off = 128; off > 0; off >>= 1) {
        if (threadIdx.x < off) sred[threadIdx.x] += sred[threadIdx.x + off];
        __syncthreads();
    }
    if (threadIdx.x == 0) g_f0part[blockIdx.x] = sred[0];
}

// ---- combine f0 + phase table ----------------------------------------------
__global__ void k_f0b() {
    __shared__ double sred[256];
    __shared__ double s_scale;
    sred[threadIdx.x] = g_f0part[threadIdx.x];
    __syncthreads();
    for (int off = 128; off > 0; off >>= 1) {
        if (threadIdx.x < off) sred[threadIdx.x] += sred[threadIdx.x + off];
        __syncthreads();
    }
    if (threadIdx.x == 0) {
        g_f0sq = sred[0];
        s_scale = sqrt(SC2 / sred[0]);
    }
    __syncthreads();
    double sc = s_scale;
    for (int idx = threadIdx.x; idx < NW * 9; idx += 256) {
        int w = idx / 9, s = idx % 9;
        int u, v;
        if (w == 0)      { u = 0; v = 0; }
        else if (w <= 8) { u = 0; v = w; }
        else             { u = 1 + (w - 9) / 17; v = (w - 9) % 17; }
        int y = s / 3, x = s % 3;
        int m = (u * y + v * x) % 17;
        double ang = -2.0 * 3.14159265358979323846 * (double)m / 17.0;
        g_phase[idx] = make_float2((float)(cos(ang) * sc), (float)(sin(ang) * sc));
    }
}

// ---- Build transposed DFT planes as bf16 hi/lo into buf 0 ------------------
__global__ void k_build(const float* __restrict__ K0) {
    int w = blockIdx.y;
    int ot = (blockIdx.x / 12) * 16;
    int at = (blockIdx.x % 12) * 16;
    __shared__ float2 ph[9];
    __shared__ float sre[16][17], sim[16][17];
    if (threadIdx.x < 9) ph[threadIdx.x] = g_phase[w * 9 + threadIdx.x];
    __syncthreads();
    int o_l = threadIdx.x >> 4, a_l = threadIdx.x & 15;
    const float* kp = K0 + ((ot + o_l) * CDIM + at + a_l) * 9;
    float re = 0.f, im = 0.f;
#pragma unroll
    for (int s = 0; s < 9; s++) {
        float k = kp[s];
        re = fmaf(k, ph[s].x, re);
        im = fmaf(k, ph[s].y, im);
    }
    sre[o_l][a_l] = re;
    sim[o_l][a_l] = im;
    __syncthreads();
    int a2 = threadIdx.x >> 4, o2 = threadIdx.x & 15;
    int dst = w * MAT + (at + a2) * CDIM + ot + o2;
    ushort h, l;
    split1(sre[o2][a2], h, l);
    g_pl[0][0][dst] = h;
    g_pl[0][1][dst] = l;
    split1(sim[o2][a2], h, l);
    g_pl[0][2][dst] = h;
    g_pl[0][3][dst] = l;
}

// ---- Tensor-core Hermitian gram (warp-fused Gr+Gi, cp.async pipeline) ------
// grid (6, 145), block 256 (8 warps). Warp (wid&3, wid>>2) owns rows
// (wid&3)*16.. and cols (wid>>2)*32.. of BOTH Gr and Gi.
// Per buffer: planes A_{Rh,Rl,Ih,Il} (0-3), B_{Rh,Rl,Ih,Il} (4-7),
// 64 rows x 32 k (SROW=40 padded). Two buffers, cp.async prefetch.
__global__ void __launch_bounds__(256, 2) k_gram(int stage) {
    int sbuf = stage & 1;          // stage0:0 stage1:1 stage2:0
    int dbuf = sbuf ^ 1;
    const ushort* __restrict__ S0 = g_pl[sbuf][0];
    const ushort* __restrict__ S1 = g_pl[sbuf][1];
    const ushort* __restrict__ S2 = g_pl[sbuf][2];
    const ushort* __restrict__ S3 = g_pl[sbuf][3];

    int w = blockIdx.y;
    int t = blockIdx.x;            // (ai,bi): (0,0)(0,1)(0,2)(1,1)(1,2)(2,2)
    int ai, bi;
    if (t < 3)      { ai = 0; bi = t; }
    else if (t < 5) { ai = 1; bi = t - 2; }
    else            { ai = 2; bi = 2; }
    int a0g = ai * 64, b0g = bi * 64;

    extern __shared__ ushort sm16[];
    uint32 sbase = smem_u32(sm16);

    int tid = threadIdx.x;
    int wid = tid >> 5;
    int lane = tid & 31;
    int mrow = (wid & 3) * 16;
    int nbase = (wid >> 2) * 32;   // 0 or 32
    int r  = lane >> 2;
    int cp = (lane & 3) * 2;

    float accR[4][4], accI[4][4];
#pragma unroll
    for (int nt = 0; nt < 4; nt++)
#pragma unroll
        for (int q = 0; q < 4; q++) { accR[nt][q] = 0.f; accI[nt][q] = 0.f; }

    // issue one chunk's cp.async copies into buffer `buf`
    auto issue = [&](int c, int buf) {
        int kb = c * KCH;
#pragma unroll
        for (int i = 0; i < 8; i++) {
            int pid = i * 256 + tid;        // 0..2047
            int seg = pid & 3;              // 16B segment (8 elems)
            int row = (pid >> 2) & 127;     // 0..127 (A rows then B rows)
            int p = pid >> 9;               // src plane 0..3
            int grow = (row < 64) ? (a0g + row) : (b0g + row - 64);
            const ushort* sp = (p == 0) ? S0 : (p == 1) ? S1 : (p == 2) ? S2 : S3;
            const ushort* g = sp + w * MAT + grow * CDIM + kb + seg * 8;
            uint32 dst = sbase + 2u * (uint32)(buf * BUFE +
                (p + ((row < 64) ? 0 : 4)) * PL + (row & 63) * SROW + seg * 8);
            CP_ASYNC16(dst, g);
        }
    };

    issue(0, 0);
    CP_COMMIT();

    for (int c = 0; c < 6; c++) {
        if (c < 5) {
            issue(c + 1, (c + 1) & 1);
            CP_COMMIT();
            CP_WAIT1();
        } else {
            CP_WAIT0();
        }
        __syncthreads();

        int bb = (c & 1) * BUFE;
        const int aRh = bb, aRl = bb + PL, aIh = bb + 2*PL, aIl = bb + 3*PL;
        const int bRh = bb + 4*PL, bRl = bb + 5*PL;
        const int bIh = bb + 6*PL, bIl = bb + 7*PL;

#pragma unroll
        for (int ks = 0; ks < 2; ks++) {
            int k0 = ks * 16;
            int ao = (mrow + r) * SROW + k0 + cp;
            uint32 fRh[4], fRl[4], fIh[4], fIl[4], fNh[4], fNl[4];
            fRh[0] = *(const uint32*)&sm16[aRh + ao];
            fRh[1] = *(const uint32*)&sm16[aRh + ao + 8*SROW];
            fRh[2] = *(const uint32*)&sm16[aRh + ao + 8];
            fRh[3] = *(const uint32*)&sm16[aRh + ao + 8*SROW + 8];
            fRl[0] = *(const uint32*)&sm16[aRl + ao];
            fRl[1] = *(const uint32*)&sm16[aRl + ao + 8*SROW];
            fRl[2] = *(const uint32*)&sm16[aRl + ao + 8];
            fRl[3] = *(const uint32*)&sm16[aRl + ao + 8*SROW + 8];
            fIh[0] = *(const uint32*)&sm16[aIh + ao];
            fIh[1] = *(const uint32*)&sm16[aIh + ao + 8*SROW];
            fIh[2] = *(const uint32*)&sm16[aIh + ao + 8];
            fIh[3] = *(const uint32*)&sm16[aIh + ao + 8*SROW + 8];
            fIl[0] = *(const uint32*)&sm16[aIl + ao];
            fIl[1] = *(const uint32*)&sm16[aIl + ao + 8*SROW];
            fIl[2] = *(const uint32*)&sm16[aIl + ao + 8];
            fIl[3] = *(const uint32*)&sm16[aIl + ao + 8*SROW + 8];
#pragma unroll
            for (int q = 0; q < 4; q++) {
                fNh[q] = fIh[q] ^ 0x80008000u;
                fNl[q] = fIl[q] ^ 0x80008000u;
            }
#pragma unroll
            for (int nt = 0; nt < 4; nt++) {
                int bbo = (nbase + nt * 8 + r) * SROW + k0 + cp;
                uint32 rh0 = *(const uint32*)&sm16[bRh + bbo];
                uint32 rh1 = *(const uint32*)&sm16[bRh + bbo + 8];
                uint32 rl0 = *(const uint32*)&sm16[bRl + bbo];
                uint32 rl1 = *(const uint32*)&sm16[bRl + bbo + 8];
                uint32 ih0 = *(const uint32*)&sm16[bIh + bbo];
                uint32 ih1 = *(const uint32*)&sm16[bIh + bbo + 8];
                uint32 il0 = *(const uint32*)&sm16[bIl + bbo];
                uint32 il1 = *(const uint32*)&sm16[bIl + bbo + 8];
                // Gr = R·R^T + I·I^T
                mma16816(accR[nt], fRh, rh0, rh1);
                mma16816(accR[nt], fRh, rl0, rl1);
                mma16816(accR[nt], fRl, rh0, rh1);
                mma16816(accR[nt], fIh, ih0, ih1);
                mma16816(accR[nt], fIh, il0, il1);
                mma16816(accR[nt], fIl, ih0, ih1);
                // Gi = R·I^T + (−I)·R^T
                mma16816(accI[nt], fRh, ih0, ih1);
                mma16816(accI[nt], fRh, il0, il1);
                mma16816(accI[nt], fRl, ih0, ih1);
                mma16816(accI[nt], fNh, rh0, rh1);
                mma16816(accI[nt], fNh, rl0, rl1);
                mma16816(accI[nt], fNl, rh0, rh1);
            }
        }
        __syncthreads();
    }

    // ---- epilogue: split to bf16 hi/lo dst planes (+ conj mirror), norms ----
    bool offdiag = (ai != bi);
    bool wr = (stage != 2);
    ushort* RH = g_pl[dbuf][0] + w * MAT;
    ushort* RL = g_pl[dbuf][1] + w * MAT;
    ushort* IH = g_pl[dbuf][2] + w * MAT;
    ushort* IL = g_pl[dbuf][3] + w * MAT;
    float ns = 0.f;
#pragma unroll
    for (int nt = 0; nt < 4; nt++) {
        int gr0 = a0g + mrow + r;
        int gc0 = b0g + nbase + nt * 8 + cp;
#pragma unroll
        for (int half = 0; half < 2; half++) {
            float vr0 = accR[nt][half * 2], vr1 = accR[nt][half * 2 + 1];
            float vi0 = accI[nt][half * 2], vi1 = accI[nt][half * 2 + 1];
            ns = fmaf(vr0, vr0, ns); ns = fmaf(vr1, vr1, ns);
            ns = fmaf(vi0, vi0, ns); ns = fmaf(vi1, vi1, ns);
            if (wr) {
                int gr = gr0 + half * 8;
                ushort rh0, rl0, rh1, rl1, ih0, il0, ih1, il1;
                split1(vr0, rh0, rl0); split1(vr1, rh1, rl1);
                split1(vi0, ih0, il0); split1(vi1, ih1, il1);
                *(uint32*)&RH[gr * CDIM + gc0] = (uint32)rh0 | ((uint32)rh1 << 16);
                *(uint32*)&RL[gr * CDIM + gc0] = (uint32)rl0 | ((uint32)rl1 << 16);
                *(uint32*)&IH[gr * CDIM + gc0] = (uint32)ih0 | ((uint32)ih1 << 16);
                *(uint32*)&IL[gr * CDIM + gc0] = (uint32)il0 | ((uint32)il1 << 16);
                if (offdiag) {   // Gr symmetric, Gi antisymmetric
                    RH[gc0 * CDIM + gr]       = rh0;
                    RL[gc0 * CDIM + gr]       = rl0;
                    RH[(gc0 + 1) * CDIM + gr] = rh1;
                    RL[(gc0 + 1) * CDIM + gr] = rl1;
                    IH[gc0 * CDIM + gr]       = ih0 ^ 0x8000;
                    IL[gc0 * CDIM + gr]       = il0 ^ 0x8000;
                    IH[(gc0 + 1) * CDIM + gr] = ih1 ^ 0x8000;
                    IL[(gc0 + 1) * CDIM + gr] = il1 ^ 0x8000;
                }
            }
        }
    }

    double* red = (double*)sm16;     // buffers dead
    red[tid] = (double)ns;
    __syncthreads();
    for (int off = 128; off > 0; off >>= 1) {
        if (tid < off) red[tid] += red[tid + off];
        __syncthreads();
    }
    if (tid == 0) {
        double wgt = ((w == 0) ? 1.0 : 2.0) * (offdiag ? 2.0 : 1.0);
        g_part[stage][w * NTILE + t] = wgt * red[0];
    }
}

// ---- Deterministic final reduction + sigma ---------------------------------
__global__ void k_sigma() {
    __shared__ double sred[256];
    double m[3];
    for (int s = 0; s < 3; s++) {
        double acc = 0.0;
        for (int i = threadIdx.x; i < NPART; i += 256) acc += g_part[s][i];
        sred[threadIdx.x] = acc;
        __syncthreads();
        for (int off = 128; off > 0; off >>= 1) {
            if (threadIdx.x < off) sred[threadIdx.x] += sred[threadIdx.x + off];
            __syncthreads();
        }
        m[s] = sred[0];
        __syncthreads();
    }
    if (threadIdx.x == 0) {
        double f0 = sqrt(g_f0sq);
        double f1 = sqrt(m[0] / NTOT2) / SC2;
        double f2 = sqrt(m[1] / NTOT2) / (SC2 * SC2 * f1 * f1);
        double ff = sqrt(m[2] / NTOT2) /
                    (SC2 * SC2 * SC2 * SC2 * f1 * f1 * f1 * f1 * f2 * f2);
        double logs = log(f0) + 0.5 * log(f1) + 0.25 * log(f2) + 0.125 * log(ff);
        g_inv_sigma = exp(-logs);
    }
}

__global__ void k_scale(const float* __restrict__ K0, float* __restrict__ out,
                        int n) {
    float s = (float)g_inv_sigma;
    int i = blockIdx.x * 256 + threadIdx.x;
    if (i < n) out[i] = K0[i] * s;
}

extern "C" void kernel_launch(void* const* d_in, const int* in_sizes, int n_in,
                              void* d_out, int out_size) {
    const float* K0 = (const float*)d_in[0];
    float* out = (float*)d_out;
    int n = in_sizes[0];   // 331776

    cudaFuncSetAttribute(k_gram, cudaFuncAttributeMaxDynamicSharedMemorySize,
                         SMEM_DYN);

    k_f0a<<<F0BLK, 256>>>(K0, n);
    k_f0b<<<1, 256>>>();
    k_build<<<dim3(144, NW), 256>>>(K0);
    k_gram<<<dim3(NTILE, NW), 256, SMEM_DYN>>>(0);
    k_gram<<<dim3(NTILE, NW), 256, SMEM_DYN>>>(1);
    k_gram<<<dim3(NTILE, NW), 256, SMEM_DYN>>>(2);
    k_sigma<<<1, 256>>>();
    k_scale<<<(n + 255) / 256, 256>>>(K0, out, n);
}

// round 17
// speedup vs baseline: 1.0751x; 1.0751x over previous
#include <cuda_runtime.h>
#include <cuda_bf16.h>
#include <math.h>
#include <stdint.h>

// ---------------------------------------------------------------------------
// PowerIterationConv: sigma via Gram iteration in the DFT domain, grams on
// tensor cores via mma.sync m16n8k16 bf16 (fp32 accum).
//
//   Gr = R·R^T + I·I^T,  Gi = R·I^T − I·R^T  (G Hermitian every stage ->
//   6-of-9 64x64 tiles + conjugate mirror writes).  bf16 2-way split
//   (hi+lo), 3 MMAs per real product (lo·lo dropped).
//
// R17: R15 base (warp-fused Gr+Gi, conflict-free scalar LDS, KCH=64).
// Stage 2 runs hi-only (1 MMA per real product instead of 3; error enters
// sigma with weight 1/8 via m2 only -> ~1e-5 expected, well under 1e-3),
// and copies only the 2 hi planes.
// ---------------------------------------------------------------------------

#define CDIM 192
#define MAT (CDIM*CDIM)
#define NW 145
#define NTOT2 289.0
#define SC2 48.0
#define NTILE 6
#define NPART (NTILE*NW)        // 870
#define F0BLK 256

#define KCH 64                  // k-chunk (3 chunks cover K=192)
#define SROW 72                 // padded bf16 row stride (36 words: 4 mod 8)
#define PL (64*SROW)            // plane elems (4608)
#define SMEM_DYN (8*PL*2)       // 73728 bytes

typedef unsigned int uint32;

// bf16 hi/lo planes, double-buffered across stages. plane: 0=Rh 1=Rl 2=Ih 3=Il
__device__ ushort g_pl[2][4][NW*MAT];
__device__ double g_f0sq;
__device__ double g_f0part[F0BLK];
__device__ double g_part[3][NPART];
__device__ double g_inv_sigma;
__device__ float2 g_phase[NW*9];

__device__ __forceinline__ void mma16816(float* d, const uint32* a,
                                         uint32 b0, uint32 b1) {
    asm volatile(
        "mma.sync.aligned.m16n8k16.row.col.f32.bf16.bf16.f32 "
        "{%0,%1,%2,%3}, {%4,%5,%6,%7}, {%8,%9}, {%0,%1,%2,%3};"
        : "+f"(d[0]), "+f"(d[1]), "+f"(d[2]), "+f"(d[3])
        : "r"(a[0]), "r"(a[1]), "r"(a[2]), "r"(a[3]), "r"(b0), "r"(b1));
}
__device__ __forceinline__ void split1(float v, ushort& h, ushort& l) {
    __nv_bfloat16 hb = __float2bfloat16(v);
    __nv_bfloat16 lb = __float2bfloat16(v - __bfloat162float(hb));
    h = __bfloat16_as_ushort(hb);
    l = __bfloat16_as_ushort(lb);
}

// ---- ||K0||_F^2 partials ---------------------------------------------------
__global__ void k_f0a(const float* __restrict__ K0, int n) {
    __shared__ double sred[256];
    int per = (n + F0BLK - 1) / F0BLK;
    int base = blockIdx.x * per;
    int end = min(base + per, n);
    double s = 0.0;
    for (int i = base + threadIdx.x; i < end; i += 256) {
        float v = K0[i];
        s += (double)v * (double)v;
    }
    sred[threadIdx.x] = s;
    __syncthreads();
    for (int off = 128; off > 0; off >>= 1) {
        if (threadIdx.x < off) sred[threadIdx.x] += sred[threadIdx.x + off];
        __syncthreads();
    }
    if (threadIdx.x == 0) g_f0part[blockIdx.x] = sred[0];
}

// ---- combine f0 + phase table ----------------------------------------------
__global__ void k_f0b() {
    __shared__ double sred[256];
    __shared__ double s_scale;
    sred[threadIdx.x] = g_f0part[threadIdx.x];
    __syncthreads();
    for (int off = 128; off > 0; off >>= 1) {
        if (threadIdx.x < off) sred[threadIdx.x] += sred[threadIdx.x + off];
        __syncthreads();
    }
    if (threadIdx.x == 0) {
        g_f0sq = sred[0];
        s_scale = sqrt(SC2 / sred[0]);
    }
    __syncthreads();
    double sc = s_scale;
    for (int idx = threadIdx.x; idx < NW * 9; idx += 256) {
        int w = idx / 9, s = idx % 9;
        int u, v;
        if (w == 0)      { u = 0; v = 0; }
        else if (w <= 8) { u = 0; v = w; }
        else             { u = 1 + (w - 9) / 17; v = (w - 9) % 17; }
        int y = s / 3, x = s % 3;
        int m = (u * y + v * x) % 17;
        double ang = -2.0 * 3.14159265358979323846 * (double)m / 17.0;
        g_phase[idx] = make_float2((float)(cos(ang) * sc), (float)(sin(ang) * sc));
    }
}

// ---- Build transposed DFT planes as bf16 hi/lo into buf 0 ------------------
__global__ void k_build(const float* __restrict__ K0) {
    int w = blockIdx.y;
    int ot = (blockIdx.x / 12) * 16;
    int at = (blockIdx.x % 12) * 16;
    __shared__ float2 ph[9];
    __shared__ float sre[16][17], sim[16][17];
    if (threadIdx.x < 9) ph[threadIdx.x] = g_phase[w * 9 + threadIdx.x];
    __syncthreads();
    int o_l = threadIdx.x >> 4, a_l = threadIdx.x & 15;
    const float* kp = K0 + ((ot + o_l) * CDIM + at + a_l) * 9;
    float re = 0.f, im = 0.f;
#pragma unroll
    for (int s = 0; s < 9; s++) {
        float k = kp[s];
        re = fmaf(k, ph[s].x, re);
        im = fmaf(k, ph[s].y, im);
    }
    sre[o_l][a_l] = re;
    sim[o_l][a_l] = im;
    __syncthreads();
    int a2 = threadIdx.x >> 4, o2 = threadIdx.x & 15;
    int dst = w * MAT + (at + a2) * CDIM + ot + o2;
    ushort h, l;
    split1(sre[o2][a2], h, l);
    g_pl[0][0][dst] = h;
    g_pl[0][1][dst] = l;
    split1(sim[o2][a2], h, l);
    g_pl[0][2][dst] = h;
    g_pl[0][3][dst] = l;
}

// ---- Tensor-core Hermitian gram (warp-fused Gr+Gi) -------------------------
// grid (6, 145), block 256 (8 warps). Warp (wid&3, wid>>2) owns rows
// (wid&3)*16.. and cols (wid>>2)*32.. of BOTH Gr and Gi.
// smem planes: A_{Rh,Rl,Ih,Il} (0-3), B_{Rh,Rl,Ih,Il} (4-7), 64 x 64 bf16
// rows padded to SROW=72.  Stage 2: hi-only (planes 0,2 / 4,6; 4 MMAs/group).
__global__ void __launch_bounds__(256, 2) k_gram(int stage) {
    int sbuf = stage & 1;          // stage0:0 stage1:1 stage2:0
    int dbuf = sbuf ^ 1;
    const ushort* __restrict__ S0 = g_pl[sbuf][0];
    const ushort* __restrict__ S1 = g_pl[sbuf][1];
    const ushort* __restrict__ S2 = g_pl[sbuf][2];
    const ushort* __restrict__ S3 = g_pl[sbuf][3];

    int w = blockIdx.y;
    int t = blockIdx.x;            // (ai,bi): (0,0)(0,1)(0,2)(1,1)(1,2)(2,2)
    int ai, bi;
    if (t < 3)      { ai = 0; bi = t; }
    else if (t < 5) { ai = 1; bi = t - 2; }
    else            { ai = 2; bi = 2; }
    int a0g = ai * 64, b0g = bi * 64;

    extern __shared__ ushort sm16[];

    int tid = threadIdx.x;
    int wid = tid >> 5;
    int lane = tid & 31;
    int mrow = (wid & 3) * 16;
    int nbase = (wid >> 2) * 32;   // 0 or 32
    int r  = lane >> 2;
    int cp = (lane & 3) * 2;

    bool full = (stage != 2);

    float accR[4][4], accI[4][4];
#pragma unroll
    for (int nt = 0; nt < 4; nt++)
#pragma unroll
        for (int q = 0; q < 4; q++) { accR[nt][q] = 0.f; accI[nt][q] = 0.f; }

    const int aRh = 0, aRl = PL, aIh = 2*PL, aIl = 3*PL;
    const int bRh = 4*PL, bRl = 5*PL, bIh = 6*PL, bIl = 7*PL;

    for (int c = 0; c < 3; c++) {
        int kb = c * KCH;
        if (full) {
            // copy all 4 src planes: 4 x 128 rows x 4 segs x 16 elems
#pragma unroll
            for (int i = 0; i < 8; i++) {
                int pid = i * 256 + tid;       // 0..2047
                int p = pid >> 9;              // src plane 0..3
                int rem = pid & 511;
                int row = rem >> 2;            // 0..127
                int seg = rem & 3;
                int grow = (row < 64) ? (a0g + row) : (b0g + row - 64);
                const ushort* sp = (p == 0) ? S0 : (p == 1) ? S1 : (p == 2) ? S2 : S3;
                const ushort* g = sp + w * MAT + grow * CDIM + kb + seg * 16;
                uint4 v0 = *(const uint4*)g;
                uint4 v1 = *(const uint4*)(g + 8);
                int db = (p + ((row < 64) ? 0 : 4)) * PL + (row & 63) * SROW + seg * 16;
                *(uint4*)&sm16[db]     = v0;
                *(uint4*)&sm16[db + 8] = v1;
            }
        } else {
            // stage 2: copy only hi planes (Rh, Ih)
#pragma unroll
            for (int i = 0; i < 4; i++) {
                int pid = i * 256 + tid;       // 0..1023
                int p01 = pid >> 9;            // 0:Rh 1:Ih
                int rem = pid & 511;
                int row = rem >> 2;
                int seg = rem & 3;
                int grow = (row < 64) ? (a0g + row) : (b0g + row - 64);
                const ushort* sp = p01 ? S2 : S0;
                const ushort* g = sp + w * MAT + grow * CDIM + kb + seg * 16;
                uint4 v0 = *(const uint4*)g;
                uint4 v1 = *(const uint4*)(g + 8);
                int db = (p01 * 2 + ((row < 64) ? 0 : 4)) * PL +
                         (row & 63) * SROW + seg * 16;
                *(uint4*)&sm16[db]     = v0;
                *(uint4*)&sm16[db + 8] = v1;
            }
        }
        __syncthreads();

        if (full) {
            // ---- full path: 12 MMAs per (nt, kstep) ----
#pragma unroll 1
            for (int ks = 0; ks < 4; ks++) {
                int k0 = ks * 16;
                int ao = (mrow + r) * SROW + k0 + cp;
                uint32 fRh[4], fRl[4], fIh[4], fIl[4], fNh[4], fNl[4];
                fRh[0] = *(const uint32*)&sm16[aRh + ao];
                fRh[1] = *(const uint32*)&sm16[aRh + ao + 8*SROW];
                fRh[2] = *(const uint32*)&sm16[aRh + ao + 8];
                fRh[3] = *(const uint32*)&sm16[aRh + ao + 8*SROW + 8];
                fRl[0] = *(const uint32*)&sm16[aRl + ao];
                fRl[1] = *(const uint32*)&sm16[aRl + ao + 8*SROW];
                fRl[2] = *(const uint32*)&sm16[aRl + ao + 8];
                fRl[3] = *(const uint32*)&sm16[aRl + ao + 8*SROW + 8];
                fIh[0] = *(const uint32*)&sm16[aIh + ao];
                fIh[1] = *(const uint32*)&sm16[aIh + ao + 8*SROW];
                fIh[2] = *(const uint32*)&sm16[aIh + ao + 8];
                fIh[3] = *(const uint32*)&sm16[aIh + ao + 8*SROW + 8];
                fIl[0] = *(const uint32*)&sm16[aIl + ao];
                fIl[1] = *(const uint32*)&sm16[aIl + ao + 8*SROW];
                fIl[2] = *(const uint32*)&sm16[aIl + ao + 8];
                fIl[3] = *(const uint32*)&sm16[aIl + ao + 8*SROW + 8];
#pragma unroll
                for (int q = 0; q < 4; q++) {
                    fNh[q] = fIh[q] ^ 0x80008000u;
                    fNl[q] = fIl[q] ^ 0x80008000u;
                }
#pragma unroll
                for (int nt = 0; nt < 4; nt++) {
                    int bb = (nbase + nt * 8 + r) * SROW + k0 + cp;
                    uint32 rh0 = *(const uint32*)&sm16[bRh + bb];
                    uint32 rh1 = *(const uint32*)&sm16[bRh + bb + 8];
                    uint32 rl0 = *(const uint32*)&sm16[bRl + bb];
                    uint32 rl1 = *(const uint32*)&sm16[bRl + bb + 8];
                    uint32 ih0 = *(const uint32*)&sm16[bIh + bb];
                    uint32 ih1 = *(const uint32*)&sm16[bIh + bb + 8];
                    uint32 il0 = *(const uint32*)&sm16[bIl + bb];
                    uint32 il1 = *(const uint32*)&sm16[bIl + bb + 8];
                    // Gr = R·R^T + I·I^T
                    mma16816(accR[nt], fRh, rh0, rh1);
                    mma16816(accR[nt], fRh, rl0, rl1);
                    mma16816(accR[nt], fRl, rh0, rh1);
                    mma16816(accR[nt], fIh, ih0, ih1);
                    mma16816(accR[nt], fIh, il0, il1);
                    mma16816(accR[nt], fIl, ih0, ih1);
                    // Gi = R·I^T + (−I)·R^T
                    mma16816(accI[nt], fRh, ih0, ih1);
                    mma16816(accI[nt], fRh, il0, il1);
                    mma16816(accI[nt], fRl, ih0, ih1);
                    mma16816(accI[nt], fNh, rh0, rh1);
                    mma16816(accI[nt], fNh, rl0, rl1);
                    mma16816(accI[nt], fNl, rh0, rh1);
                }
            }
        } else {
            // ---- stage-2 fast path: hi-only, 4 MMAs per (nt, kstep) ----
#pragma unroll 1
            for (int ks = 0; ks < 4; ks++) {
                int k0 = ks * 16;
                int ao = (mrow + r) * SROW + k0 + cp;
                uint32 fRh[4], fIh[4], fNh[4];
                fRh[0] = *(const uint32*)&sm16[aRh + ao];
                fRh[1] = *(const uint32*)&sm16[aRh + ao + 8*SROW];
                fRh[2] = *(const uint32*)&sm16[aRh + ao + 8];
                fRh[3] = *(const uint32*)&sm16[aRh + ao + 8*SROW + 8];
                fIh[0] = *(const uint32*)&sm16[aIh + ao];
                fIh[1] = *(const uint32*)&sm16[aIh + ao + 8*SROW];
                fIh[2] = *(const uint32*)&sm16[aIh + ao + 8];
                fIh[3] = *(const uint32*)&sm16[aIh + ao + 8*SROW + 8];
#pragma unroll
                for (int q = 0; q < 4; q++) fNh[q] = fIh[q] ^ 0x80008000u;
#pragma unroll
                for (int nt = 0; nt < 4; nt++) {
                    int bb = (nbase + nt * 8 + r) * SROW + k0 + cp;
                    uint32 rh0 = *(const uint32*)&sm16[bRh + bb];
                    uint32 rh1 = *(const uint32*)&sm16[bRh + bb + 8];
                    uint32 ih0 = *(const uint32*)&sm16[bIh + bb];
                    uint32 ih1 = *(const uint32*)&sm16[bIh + bb + 8];
                    mma16816(accR[nt], fRh, rh0, rh1);
                    mma16816(accR[nt], fIh, ih0, ih1);
                    mma16816(accI[nt], fRh, ih0, ih1);
                    mma16816(accI[nt], fNh, rh0, rh1);
                }
            }
        }
        __syncthreads();
    }

    // ---- epilogue: split to bf16 hi/lo dst planes (+ conj mirror), norms ----
    bool offdiag = (ai != bi);
    bool wr = (stage != 2);
    ushort* RH = g_pl[dbuf][0] + w * MAT;
    ushort* RL = g_pl[dbuf][1] + w * MAT;
    ushort* IH = g_pl[dbuf][2] + w * MAT;
    ushort* IL = g_pl[dbuf][3] + w * MAT;
    float ns = 0.f;
#pragma unroll
    for (int nt = 0; nt < 4; nt++) {
        int gr0 = a0g + mrow + r;
        int gc0 = b0g + nbase + nt * 8 + cp;
#pragma unroll
        for (int half = 0; half < 2; half++) {
            float vr0 = accR[nt][half * 2], vr1 = accR[nt][half * 2 + 1];
            float vi0 = accI[nt][half * 2], vi1 = accI[nt][half * 2 + 1];
            ns = fmaf(vr0, vr0, ns); ns = fmaf(vr1, vr1, ns);
            ns = fmaf(vi0, vi0, ns); ns = fmaf(vi1, vi1, ns);
            if (wr) {
                int gr = gr0 + half * 8;
                ushort rh0, rl0, rh1, rl1, ih0, il0, ih1, il1;
                split1(vr0, rh0, rl0); split1(vr1, rh1, rl1);
                split1(vi0, ih0, il0); split1(vi1, ih1, il1);
                *(uint32*)&RH[gr * CDIM + gc0] = (uint32)rh0 | ((uint32)rh1 << 16);
                *(uint32*)&RL[gr * CDIM + gc0] = (uint32)rl0 | ((uint32)rl1 << 16);
                *(uint32*)&IH[gr * CDIM + gc0] = (uint32)ih0 | ((uint32)ih1 << 16);
                *(uint32*)&IL[gr * CDIM + gc0] = (uint32)il0 | ((uint32)il1 << 16);
                if (offdiag) {   // Gr symmetric, Gi antisymmetric
                    RH[gc0 * CDIM + gr]       = rh0;
                    RL[gc0 * CDIM + gr]       = rl0;
                    RH[(gc0 + 1) * CDIM + gr] = rh1;
                    RL[(gc0 + 1) * CDIM + gr] = rl1;
                    IH[gc0 * CDIM + gr]       = ih0 ^ 0x8000;
                    IL[gc0 * CDIM + gr]       = il0 ^ 0x8000;
                    IH[(gc0 + 1) * CDIM + gr] = ih1 ^ 0x8000;
                    IL[(gc0 + 1) * CDIM + gr] = il1 ^ 0x8000;
                }
            }
        }
    }

    double* red = (double*)sm16;     // planes dead
    red[tid] = (double)ns;
    __syncthreads();
    for (int off = 128; off > 0; off >>= 1) {
        if (tid < off) red[tid] += red[tid + off];
        __syncthreads();
    }
    if (tid == 0) {
        double wgt = ((w == 0) ? 1.0 : 2.0) * (offdiag ? 2.0 : 1.0);
        g_part[stage][w * NTILE + t] = wgt * red[0];
    }
}

// ---- Deterministic final reduction + sigma ---------------------------------
__global__ void k_sigma() {
    __shared__ double sred[256];
    double m[3];
    for (int s = 0; s < 3; s++) {
        double acc = 0.0;
        for (int i = threadIdx.x; i < NPART; i += 256) acc += g_part[s][i];
        sred[threadIdx.x] = acc;
        __syncthreads();
        for (int off = 128; off > 0; off >>= 1) {
            if (threadIdx.x < off) sred[threadIdx.x] += sred[threadIdx.x + off];
            __syncthreads();
        }
        m[s] = sred[0];
        __syncthreads();
    }
    if (threadIdx.x == 0) {
        double f0 = sqrt(g_f0sq);
        double f1 = sqrt(m[0] / NTOT2) / SC2;
        double f2 = sqrt(m[1] / NTOT2) / (SC2 * SC2 * f1 * f1);
        double ff = sqrt(m[2] / NTOT2) /
                    (SC2 * SC2 * SC2 * SC2 * f1 * f1 * f1 * f1 * f2 * f2);
        double logs = log(f0) + 0.5 * log(f1) + 0.25 * log(f2) + 0.125 * log(ff);
        g_inv_sigma = exp(-logs);
    }
}

__global__ void k_scale(const float* __restrict__ K0, float* __restrict__ out,
                        int n) {
    float s = (float)g_inv_sigma;
    int i = blockIdx.x * 256 + threadIdx.x;
    if (i < n) out[i] = K0[i] * s;
}

extern "C" void kernel_launch(void* const* d_in, const int* in_sizes, int n_in,
                              void* d_out, int out_size) {
    const float* K0 = (const float*)d_in[0];
    float* out = (float*)d_out;
    int n = in_sizes[0];   // 331776

    cudaFuncSetAttribute(k_gram, cudaFuncAttributeMaxDynamicSharedMemorySize,
                         SMEM_DYN);

    k_f0a<<<F0BLK, 256>>>(K0, n);
    k_f0b<<<1, 256>>>();
    k_build<<<dim3(144, NW), 256>>>(K0);
    k_gram<<<dim3(NTILE, NW), 256, SMEM_DYN>>>(0);
    k_gram<<<dim3(NTILE, NW), 256, SMEM_DYN>>>(1);
    k_gram<<<dim3(NTILE, NW), 256, SMEM_DYN>>>(2);
    k_sigma<<<1, 256>>>();
    k_scale<<<(n + 255) / 256, 256>>>(K0, out, n);
}